// round 11
// baseline (speedup 1.0000x reference)
#include <cuda_runtime.h>
#include <cuda_bf16.h>
#include <stdint.h>

// SelectiveLinear: out[b,:] = X[b,:] @ W[idx[b]] + bias[idx[b]]
// B=2048, IN=512, OUT=512, H=16.
// R11: occupancy x2. R10 evidence: gemm 31.9us, occ 19.5% (12 warps/SM),
// tensor 21%, issue 22% -> latency-bound. Reshape GEMM block: 8 warps,
// warp tile 16x64 (acc 32 regs), same M=64/N=128 tile, same 3-stage pipeline,
// split-K over 3 bf16 terms with atomicAdd reduction.

#define IN_DIM  512
#define OUT_DIM 512
#define NHEADS  16
#define MAXB    2048
#define KPACK   1024            // g_A row: [hi(512) | lo(512)] bf16
#define NCHUNK_T 16             // chunks per term (each 32 k)
#define A_STRIDE_B 80           // A smem row stride bytes (64B data + 16B pad)
#define B_STRIDE_B 272          // B smem row stride bytes (256B data + 16B pad)
#define A_TILE_B  (64 * A_STRIDE_B)    // 5120
#define B_TILE_B  (32 * B_STRIDE_B)    // 8704
#define STAGE_B   (A_TILE_B + B_TILE_B) // 13824; 3 stages = 41472 (static OK)

__device__ int g_rows[MAXB];
__device__ int g_off[NHEADS + 1];
__device__ int g_is64;
__device__ __align__(256) __nv_bfloat16 g_A[(size_t)MAXB * KPACK];                   // 4MB
__device__ __align__(256) __nv_bfloat16 g_Bw[(size_t)NHEADS * 2 * IN_DIM * OUT_DIM]; // 16MB

__device__ __forceinline__ uint32_t smem_u32(const void* p) {
    uint32_t a;
    asm("{ .reg .u64 t; cvta.to.shared.u64 t, %1; cvt.u32.u64 %0, t; }"
        : "=r"(a) : "l"(p));
    return a;
}
__device__ __forceinline__ void cpasync16(uint32_t dst, const void* src) {
    asm volatile("cp.async.cg.shared.global [%0], [%1], 16;" :: "r"(dst), "l"(src) : "memory");
}
#define CP_COMMIT() asm volatile("cp.async.commit_group;" ::: "memory")
#define CP_WAIT0()  asm volatile("cp.async.wait_group 0;" ::: "memory")
#define CP_WAIT1()  asm volatile("cp.async.wait_group 1;" ::: "memory")

__device__ __forceinline__ int load_idx(const int* __restrict__ w, int b, int is64) {
    return w[is64 ? (b << 1) : b];
}

// ---------------------------------------------------------------------------
// Kernel 1: prep.
//   bx == 0                : idx dtype sniff + bucket-by-head
//   bx in [1, XB]          : X -> bf16 hi|lo (at original row)
//   bx in (XB, XB+512]     : W -> bf16 hi|lo  [h][sel][k][n]
//   bx in (XB+512, +ZB]    : zero out[0 .. Bn*OUT) (split-K accumulators)
// ---------------------------------------------------------------------------
__global__ __launch_bounds__(256)
void prep(const float* __restrict__ X, const int* __restrict__ idx_w,
          const float* __restrict__ W, float* __restrict__ out, int Bn) {
    const int bx = blockIdx.x;
    const int tid = threadIdx.x;
    const int XB = (Bn + 7) / 8;

    if (bx == 0) {
        __shared__ int s_not;
        __shared__ int s_cnt[NHEADS];
        __shared__ int s_base[NHEADS];
        if (tid == 0) s_not = 0;
        __syncthreads();
        for (int i = tid; i < Bn; i += 256) {
            int v = idx_w[i];
            if (i & 1) { if (v != 0) s_not = 1; }
            else       { if (v < 0 || v >= NHEADS) s_not = 1; }
        }
        __syncthreads();
        const int is64 = s_not ? 0 : 1;
        if (tid == 0) g_is64 = is64;
        if (tid < NHEADS) s_cnt[tid] = 0;
        __syncthreads();
        for (int b = tid; b < Bn; b += 256)
            atomicAdd(&s_cnt[load_idx(idx_w, b, is64) & (NHEADS - 1)], 1);
        __syncthreads();
        if (tid == 0) {
            int acc = 0;
            for (int h = 0; h < NHEADS; h++) { g_off[h] = acc; s_base[h] = acc; acc += s_cnt[h]; }
            g_off[NHEADS] = acc;
        }
        __syncthreads();
        for (int b = tid; b < Bn; b += 256) {
            int h = load_idx(idx_w, b, is64) & (NHEADS - 1);
            g_rows[atomicAdd(&s_base[h], 1)] = b;
        }
    } else if (bx <= XB) {
        int p = (bx - 1) * 8 + (tid >> 5);
        int l = tid & 31;
        if (p >= Bn) return;
        const float4* xr = (const float4*)(X + (size_t)p * IN_DIM);
        union { __nv_bfloat16 h[16]; uint4 u[2]; } hi, lo;
#pragma unroll
        for (int q = 0; q < 4; q++) {
            float4 v = xr[l * 4 + q];
            float f[4] = {v.x, v.y, v.z, v.w};
#pragma unroll
            for (int e = 0; e < 4; e++) {
                __nv_bfloat16 hv = __float2bfloat16(f[e]);
                hi.h[q * 4 + e] = hv;
                lo.h[q * 4 + e] = __float2bfloat16(f[e] - __bfloat162float(hv));
            }
        }
        uint4* dh = (uint4*)(g_A + (size_t)p * KPACK + l * 16);
        dh[0] = hi.u[0]; dh[1] = hi.u[1];
        uint4* dl = (uint4*)(g_A + (size_t)p * KPACK + 512 + l * 16);
        dl[0] = lo.u[0]; dl[1] = lo.u[1];
    } else if (bx <= XB + 512) {
        const int wb = bx - 1 - XB;
        const int total = NHEADS * IN_DIM * (OUT_DIM / 4);
#pragma unroll
        for (int i = 0; i < 8; i++) {
            int id = wb * 2048 + i * 256 + tid;
            if (id >= total) break;
            int h   = id / (IN_DIM * (OUT_DIM / 4));
            int rem = id % (IN_DIM * (OUT_DIM / 4));
            int k   = rem / (OUT_DIM / 4);
            int n4  = rem % (OUT_DIM / 4);
            float4 v = ((const float4*)W)[(size_t)id];
            float f[4] = {v.x, v.y, v.z, v.w};
            union { __nv_bfloat16 h[4]; uint2 u; } hi, lo;
#pragma unroll
            for (int e = 0; e < 4; e++) {
                __nv_bfloat16 hv = __float2bfloat16(f[e]);
                hi.h[e] = hv;
                lo.h[e] = __float2bfloat16(f[e] - __bfloat162float(hv));
            }
            size_t basehi = (((size_t)h * 2 + 0) * IN_DIM + k) * OUT_DIM + n4 * 4;
            size_t baselo = (((size_t)h * 2 + 1) * IN_DIM + k) * OUT_DIM + n4 * 4;
            *(uint2*)(g_Bw + basehi) = hi.u;
            *(uint2*)(g_Bw + baselo) = lo.u;
        }
    } else {
        const int zb = bx - 1 - XB - 512;
        const long long nf4 = (long long)Bn * OUT_DIM / 4;
        float4 z4 = make_float4(0.f, 0.f, 0.f, 0.f);
#pragma unroll
        for (int i = 0; i < 4; i++) {
            long long id = (long long)zb * 1024 + i * 256 + tid;
            if (id < nf4) ((float4*)out)[id] = z4;
        }
    }
}

// ---------------------------------------------------------------------------
// Kernel 2: grouped GEMM, split-K over 3 bf16 terms, atomicAdd reduction.
// grid (4 n-tiles, ceil(Bn/64) m-slots, 3*NHEADS+1), 256 threads (8 warps).
// Block tile M=64, N=128; warp tile 16x64 (wm = wid&3, wn = wid>>2);
// per-term K: 16 chunks of 32 bf16; 3-stage cp.async pipeline.
// ---------------------------------------------------------------------------
__global__ __launch_bounds__(256)
void gemm_mma(const float* __restrict__ bias, float* __restrict__ out, int Bn,
              const int* __restrict__ idx_w, float* __restrict__ tail, int mode) {
    const int z = blockIdx.z;
    if (z == 3 * NHEADS) {   // fused tail echo
        if (blockIdx.x == 0 && blockIdx.y == 0 && tail != nullptr) {
            const int is64 = g_is64;
            for (int b = threadIdx.x; b < Bn; b += 256) {
                int v = load_idx(idx_w, b, is64) & (NHEADS - 1);
                if (mode == 1) tail[b] = (float)v;
                else           ((long long*)tail)[b] = (long long)v;
            }
        }
        return;
    }
    const int term = z >> 4;          // 0: hi*hi, 1: lo*hi, 2: hi*lo
    const int h    = z & 15;
    const int n0   = blockIdx.x * 128;
    const int m_begin = g_off[h] + blockIdx.y * 64;
    const int m_end   = g_off[h + 1];
    if (m_begin >= m_end) return;

    __shared__ __align__(16) char sm[3][STAGE_B];

    const int tid  = threadIdx.x;
    const int lane = tid & 31;
    const int wid  = tid >> 5;
    const int wm   = wid & 3;          // 4 warps over M (16 rows each)
    const int wn   = wid >> 2;         // 2 warps over N (64 cols each)

    float acc[8][4];
#pragma unroll
    for (int ni = 0; ni < 8; ni++)
#pragma unroll
        for (int e = 0; e < 4; e++) acc[ni][e] = 0.0f;

    // Loads: A 64 rows x 4 segs = 256 cp16 / 256 thr = 1 each;
    //        B 32 rows x 16 segs = 512 cp16 / 256 thr = 2 each.
    const int arow = tid >> 2, aseg = tid & 3;
    const int brow = tid >> 4, bseg = tid & 15;

    const int colbase = (term == 1) ? 512 : 0;   // A hi vs lo half
    const int Bsel    = (term == 2) ? 1 : 0;     // W hi vs lo plane

    const __nv_bfloat16* aSrc;
    {
        int p = m_begin + arow;
        if (p > Bn - 1) p = Bn - 1;
        aSrc = g_A + (size_t)g_rows[p] * KPACK + colbase + aseg * 8;
    }
    const __nv_bfloat16* bsrcBase =
        g_Bw + (((size_t)h * 2 + Bsel) * IN_DIM) * OUT_DIM + n0 + bseg * 8;

    auto load_chunk = [&](int c, int stg) {
        const int kk = c << 5;
        const uint32_t aB = smem_u32(&sm[stg][0]);
        const uint32_t bB = aB + A_TILE_B;
        cpasync16(aB + arow * A_STRIDE_B + aseg * 16, aSrc + kk);
#pragma unroll
        for (int i = 0; i < 2; i++) {
            int r = brow + i * 16;
            cpasync16(bB + r * B_STRIDE_B + bseg * 16,
                      bsrcBase + (size_t)(kk + r) * OUT_DIM);
        }
        CP_COMMIT();
    };

    load_chunk(0, 0);
    load_chunk(1, 1);

    for (int c = 0; c < NCHUNK_T; c++) {
        if (c + 1 < NCHUNK_T) CP_WAIT1();   // pending {c,c+1} -> drains c
        else                  CP_WAIT0();   // last chunk: full drain
        __syncthreads();

        if (c + 2 < NCHUNK_T) load_chunk(c + 2, (c + 2) % 3);

        const int stg = c % 3;
        const uint32_t aB = smem_u32(&sm[stg][0]);
        const uint32_t bB = aB + A_TILE_B;

#pragma unroll
        for (int km = 0; km < 32; km += 16) {
            uint32_t a[4];
            {
                int row = wm * 16 + (lane & 15);
                uint32_t addr = aB + row * A_STRIDE_B + km * 2 + ((lane >> 4) & 1) * 16;
                asm volatile("ldmatrix.sync.aligned.m8n8.x4.shared.b16 {%0,%1,%2,%3}, [%4];"
                    : "=r"(a[0]), "=r"(a[1]), "=r"(a[2]), "=r"(a[3])
                    : "r"(addr));
            }
            uint32_t b[8][2];
#pragma unroll
            for (int g = 0; g < 4; g++) {
                int krow = km + (lane & 7) + ((lane >> 3) & 1) * 8;
                int ncol = wn * 64 + g * 16 + ((lane >> 4) & 1) * 8;
                uint32_t addr = bB + krow * B_STRIDE_B + ncol * 2;
                asm volatile("ldmatrix.sync.aligned.m8n8.x4.trans.shared.b16 {%0,%1,%2,%3}, [%4];"
                    : "=r"(b[g * 2][0]), "=r"(b[g * 2][1]),
                      "=r"(b[g * 2 + 1][0]), "=r"(b[g * 2 + 1][1])
                    : "r"(addr));
            }
#pragma unroll
            for (int ni = 0; ni < 8; ni++) {
                asm volatile(
                    "mma.sync.aligned.m16n8k16.row.col.f32.bf16.bf16.f32 "
                    "{%0,%1,%2,%3}, {%4,%5,%6,%7}, {%8,%9}, {%0,%1,%2,%3};"
                    : "+f"(acc[ni][0]), "+f"(acc[ni][1]),
                      "+f"(acc[ni][2]), "+f"(acc[ni][3])
                    : "r"(a[0]), "r"(a[1]), "r"(a[2]), "r"(a[3]),
                      "r"(b[ni][0]), "r"(b[ni][1]));
            }
        }
    }

    // Epilogue: atomicAdd partials into out (zeroed by prep); term 0 adds bias.
    // row = wm*16 + rp*8 + (lane>>2), col = wn*64 + ni*8 + (lane&3)*2
#pragma unroll
    for (int rp = 0; rp < 2; rp++) {
        int r = wm * 16 + rp * 8 + (lane >> 2);
        int p = m_begin + r;
        if (p < m_end) {
            int bb = g_rows[p];
            float* op = out + (size_t)bb * OUT_DIM + n0 + wn * 64 + (lane & 3) * 2;
            const float* bp = bias + h * OUT_DIM + n0 + wn * 64 + (lane & 3) * 2;
#pragma unroll
            for (int ni = 0; ni < 8; ni++) {
                float v0 = acc[ni][rp * 2 + 0];
                float v1 = acc[ni][rp * 2 + 1];
                if (term == 0) { v0 += bp[ni * 8 + 0]; v1 += bp[ni * 8 + 1]; }
                atomicAdd(op + ni * 8 + 0, v0);
                atomicAdd(op + ni * 8 + 1, v1);
            }
        }
    }
}

extern "C" void kernel_launch(void* const* d_in, const int* in_sizes, int n_in,
                              void* d_out, int out_size) {
    const float* X     = (const float*)d_in[0];
    const int*   idx_w = (const int*)d_in[1];
    const float* W     = (const float*)d_in[2];
    const float* bias  = (const float*)d_in[3];
    float*       out   = (float*)d_out;

    const int Bn = in_sizes[1];

    const int XB = (Bn + 7) / 8;
    const int ZB = (int)(((long long)Bn * OUT_DIM / 4 + 1023) / 1024);
    prep<<<1 + XB + 512 + ZB, 256>>>(X, idx_w, W, out, Bn);

    long long extra = (long long)out_size - (long long)Bn * OUT_DIM;
    float* tail = nullptr;
    int mode = 0;
    if (extra >= Bn) {
        mode = (extra >= 2 * (long long)Bn) ? 2 : 1;
        tail = out + (size_t)Bn * OUT_DIM;
    }

    int m_slots = (Bn + 63) / 64;
    dim3 g(OUT_DIM / 128, m_slots, 3 * NHEADS + 1);
    gemm_mma<<<g, 256>>>(bias, out, Bn, idx_w, tail, mode);
}

// round 13
// speedup vs baseline: 1.0250x; 1.0250x over previous
#include <cuda_runtime.h>
#include <cuda_bf16.h>
#include <stdint.h>

// SelectiveLinear: out[b,:] = X[b,:] @ W[idx[b]] + bias[idx[b]]
// B=2048, IN=512, OUT=512, H=16.
// R13 = resubmission of R12 (bench infra failed twice; no kernel evidence).
// R10's proven 4-warp 32x64-warp-tile mainloop + split-K 6 ways (3 bf16 terms
// x 2 K-halves) -> ~840 working blocks; atomicAdd reduction into zeroed out.

#define IN_DIM  512
#define OUT_DIM 512
#define NHEADS  16
#define MAXB    2048
#define KPACK   1024            // g_A row: [hi(512) | lo(512)] bf16
#define NCHUNK_T 8              // chunks per block (each 32 k; one K-half)
#define A_STRIDE_B 80           // A smem row stride bytes (64B data + 16B pad)
#define B_STRIDE_B 272          // B smem row stride bytes (256B data + 16B pad)
#define A_TILE_B  (64 * A_STRIDE_B)    // 5120
#define B_TILE_B  (32 * B_STRIDE_B)    // 8704
#define STAGE_B   (A_TILE_B + B_TILE_B) // 13824; 3 stages = 41472 (static OK)

__device__ int g_rows[MAXB];
__device__ int g_off[NHEADS + 1];
__device__ int g_is64;
__device__ __align__(256) __nv_bfloat16 g_A[(size_t)MAXB * KPACK];                   // 4MB
__device__ __align__(256) __nv_bfloat16 g_Bw[(size_t)NHEADS * 2 * IN_DIM * OUT_DIM]; // 16MB

__device__ __forceinline__ uint32_t smem_u32(const void* p) {
    uint32_t a;
    asm("{ .reg .u64 t; cvta.to.shared.u64 t, %1; cvt.u32.u64 %0, t; }"
        : "=r"(a) : "l"(p));
    return a;
}
__device__ __forceinline__ void cpasync16(uint32_t dst, const void* src) {
    asm volatile("cp.async.cg.shared.global [%0], [%1], 16;" :: "r"(dst), "l"(src) : "memory");
}
#define CP_COMMIT() asm volatile("cp.async.commit_group;" ::: "memory")
#define CP_WAIT0()  asm volatile("cp.async.wait_group 0;" ::: "memory")
#define CP_WAIT1()  asm volatile("cp.async.wait_group 1;" ::: "memory")

__device__ __forceinline__ int load_idx(const int* __restrict__ w, int b, int is64) {
    return w[is64 ? (b << 1) : b];
}

// ---------------------------------------------------------------------------
// Kernel 1: prep.
//   bx == 0                : idx dtype sniff + bucket-by-head
//   bx in [1, XB]          : X -> bf16 hi|lo (at original row)
//   bx in (XB, XB+512]     : W -> bf16 hi|lo  [h][sel][k][n]
//   bx in (XB+512, +ZB]    : zero out[0 .. Bn*OUT) (split-K accumulators)
// ---------------------------------------------------------------------------
__global__ __launch_bounds__(256)
void prep(const float* __restrict__ X, const int* __restrict__ idx_w,
          const float* __restrict__ W, float* __restrict__ out, int Bn) {
    const int bx = blockIdx.x;
    const int tid = threadIdx.x;
    const int XB = (Bn + 7) / 8;

    if (bx == 0) {
        __shared__ int s_not;
        __shared__ int s_cnt[NHEADS];
        __shared__ int s_base[NHEADS];
        if (tid == 0) s_not = 0;
        __syncthreads();
        for (int i = tid; i < Bn; i += 256) {
            int v = idx_w[i];
            if (i & 1) { if (v != 0) s_not = 1; }
            else       { if (v < 0 || v >= NHEADS) s_not = 1; }
        }
        __syncthreads();
        const int is64 = s_not ? 0 : 1;
        if (tid == 0) g_is64 = is64;
        if (tid < NHEADS) s_cnt[tid] = 0;
        __syncthreads();
        for (int b = tid; b < Bn; b += 256)
            atomicAdd(&s_cnt[load_idx(idx_w, b, is64) & (NHEADS - 1)], 1);
        __syncthreads();
        if (tid == 0) {
            int acc = 0;
            for (int h = 0; h < NHEADS; h++) { g_off[h] = acc; s_base[h] = acc; acc += s_cnt[h]; }
            g_off[NHEADS] = acc;
        }
        __syncthreads();
        for (int b = tid; b < Bn; b += 256) {
            int h = load_idx(idx_w, b, is64) & (NHEADS - 1);
            g_rows[atomicAdd(&s_base[h], 1)] = b;
        }
    } else if (bx <= XB) {
        int p = (bx - 1) * 8 + (tid >> 5);
        int l = tid & 31;
        if (p >= Bn) return;
        const float4* xr = (const float4*)(X + (size_t)p * IN_DIM);
        union { __nv_bfloat16 h[16]; uint4 u[2]; } hi, lo;
#pragma unroll
        for (int q = 0; q < 4; q++) {
            float4 v = xr[l * 4 + q];
            float f[4] = {v.x, v.y, v.z, v.w};
#pragma unroll
            for (int e = 0; e < 4; e++) {
                __nv_bfloat16 hv = __float2bfloat16(f[e]);
                hi.h[q * 4 + e] = hv;
                lo.h[q * 4 + e] = __float2bfloat16(f[e] - __bfloat162float(hv));
            }
        }
        uint4* dh = (uint4*)(g_A + (size_t)p * KPACK + l * 16);
        dh[0] = hi.u[0]; dh[1] = hi.u[1];
        uint4* dl = (uint4*)(g_A + (size_t)p * KPACK + 512 + l * 16);
        dl[0] = lo.u[0]; dl[1] = lo.u[1];
    } else if (bx <= XB + 512) {
        const int wb = bx - 1 - XB;
        const int total = NHEADS * IN_DIM * (OUT_DIM / 4);
#pragma unroll
        for (int i = 0; i < 8; i++) {
            int id = wb * 2048 + i * 256 + tid;
            if (id >= total) break;
            int h   = id / (IN_DIM * (OUT_DIM / 4));
            int rem = id % (IN_DIM * (OUT_DIM / 4));
            int k   = rem / (OUT_DIM / 4);
            int n4  = rem % (OUT_DIM / 4);
            float4 v = ((const float4*)W)[(size_t)id];
            float f[4] = {v.x, v.y, v.z, v.w};
            union { __nv_bfloat16 h[4]; uint2 u; } hi, lo;
#pragma unroll
            for (int e = 0; e < 4; e++) {
                __nv_bfloat16 hv = __float2bfloat16(f[e]);
                hi.h[e] = hv;
                lo.h[e] = __float2bfloat16(f[e] - __bfloat162float(hv));
            }
            size_t basehi = (((size_t)h * 2 + 0) * IN_DIM + k) * OUT_DIM + n4 * 4;
            size_t baselo = (((size_t)h * 2 + 1) * IN_DIM + k) * OUT_DIM + n4 * 4;
            *(uint2*)(g_Bw + basehi) = hi.u;
            *(uint2*)(g_Bw + baselo) = lo.u;
        }
    } else {
        const int zb = bx - 1 - XB - 512;
        const long long nf4 = (long long)Bn * OUT_DIM / 4;
        float4 z4 = make_float4(0.f, 0.f, 0.f, 0.f);
#pragma unroll
        for (int i = 0; i < 4; i++) {
            long long id = (long long)zb * 1024 + i * 256 + tid;
            if (id < nf4) ((float4*)out)[id] = z4;
        }
    }
}

// ---------------------------------------------------------------------------
// Kernel 2: grouped GEMM, split-K 6 ways (3 terms x 2 K-halves), atomicAdd.
// grid (4 n-tiles, ceil(Bn/64) m-slots, 6*NHEADS+1), 128 threads (4 warps).
// Block tile M=64, N=128; warp tile 32x64 (wm = wid&1, wn = wid>>1);
// per-block K: 8 chunks of 32 bf16; 3-stage cp.async pipeline.
// ---------------------------------------------------------------------------
__global__ __launch_bounds__(128)
void gemm_mma(const float* __restrict__ bias, float* __restrict__ out, int Bn,
              const int* __restrict__ idx_w, float* __restrict__ tail, int mode) {
    const int z = blockIdx.z;
    if (z == 6 * NHEADS) {   // fused tail echo
        if (blockIdx.x == 0 && blockIdx.y == 0 && tail != nullptr) {
            const int is64 = g_is64;
            for (int b = threadIdx.x; b < Bn; b += 128) {
                int v = load_idx(idx_w, b, is64) & (NHEADS - 1);
                if (mode == 1) tail[b] = (float)v;
                else           ((long long*)tail)[b] = (long long)v;
            }
        }
        return;
    }
    const int tk    = z >> 4;         // 0..5
    const int term  = tk >> 1;        // 0: hi*hi, 1: lo*hi, 2: hi*lo
    const int khalf = tk & 1;         // which half of K (8 chunks each)
    const int h     = z & 15;
    const int n0    = blockIdx.x * 128;
    const int m_begin = g_off[h] + blockIdx.y * 64;
    const int m_end   = g_off[h + 1];
    if (m_begin >= m_end) return;

    __shared__ __align__(16) char sm[3][STAGE_B];

    const int tid  = threadIdx.x;
    const int lane = tid & 31;
    const int wid  = tid >> 5;
    const int wm   = wid & 1;          // 2 warps over M (32 rows each)
    const int wn   = wid >> 1;         // 2 warps over N (64 cols each)

    float acc[2][8][4];
#pragma unroll
    for (int mi = 0; mi < 2; mi++)
#pragma unroll
        for (int ni = 0; ni < 8; ni++)
#pragma unroll
            for (int e = 0; e < 4; e++) acc[mi][ni][e] = 0.0f;

    const int arow = tid >> 2, aseg = tid & 3;
    const int brow = tid >> 4, bseg = tid & 15;

    const int colbase = (term == 1) ? 512 : 0;   // A hi vs lo half
    const int Bsel    = (term == 2) ? 1 : 0;     // W hi vs lo plane
    const int kbase   = khalf * NCHUNK_T;        // chunk offset of this K-half

    const __nv_bfloat16* aSrc[2];
#pragma unroll
    for (int i = 0; i < 2; i++) {
        int p = m_begin + arow + i * 32;
        if (p > Bn - 1) p = Bn - 1;
        aSrc[i] = g_A + (size_t)g_rows[p] * KPACK + colbase + aseg * 8;
    }
    const __nv_bfloat16* bsrcBase =
        g_Bw + (((size_t)h * 2 + Bsel) * IN_DIM) * OUT_DIM + n0 + bseg * 8;

    auto load_chunk = [&](int c, int stg) {
        const int kk = (kbase + c) << 5;
        const uint32_t aB = smem_u32(&sm[stg][0]);
        const uint32_t bB = aB + A_TILE_B;
#pragma unroll
        for (int i = 0; i < 2; i++)
            cpasync16(aB + (arow + i * 32) * A_STRIDE_B + aseg * 16, aSrc[i] + kk);
#pragma unroll
        for (int i = 0; i < 4; i++) {
            int r = brow + i * 8;
            cpasync16(bB + r * B_STRIDE_B + bseg * 16,
                      bsrcBase + (size_t)(kk + r) * OUT_DIM);
        }
        CP_COMMIT();
    };

    load_chunk(0, 0);
    load_chunk(1, 1);

    for (int c = 0; c < NCHUNK_T; c++) {
        if (c + 1 < NCHUNK_T) CP_WAIT1();   // pending {c,c+1} -> drains c
        else                  CP_WAIT0();   // last chunk: full drain
        __syncthreads();

        if (c + 2 < NCHUNK_T) load_chunk(c + 2, (c + 2) % 3);

        const int stg = c % 3;
        const uint32_t aB = smem_u32(&sm[stg][0]);
        const uint32_t bB = aB + A_TILE_B;

#pragma unroll
        for (int km = 0; km < 32; km += 16) {
            uint32_t a[2][4];
#pragma unroll
            for (int mi = 0; mi < 2; mi++) {
                int row = wm * 32 + mi * 16 + (lane & 15);
                uint32_t addr = aB + row * A_STRIDE_B + km * 2 + ((lane >> 4) & 1) * 16;
                asm volatile("ldmatrix.sync.aligned.m8n8.x4.shared.b16 {%0,%1,%2,%3}, [%4];"
                    : "=r"(a[mi][0]), "=r"(a[mi][1]), "=r"(a[mi][2]), "=r"(a[mi][3])
                    : "r"(addr));
            }
            uint32_t b[8][2];
#pragma unroll
            for (int g = 0; g < 4; g++) {
                int krow = km + (lane & 7) + ((lane >> 3) & 1) * 8;
                int ncol = wn * 64 + g * 16 + ((lane >> 4) & 1) * 8;
                uint32_t addr = bB + krow * B_STRIDE_B + ncol * 2;
                asm volatile("ldmatrix.sync.aligned.m8n8.x4.trans.shared.b16 {%0,%1,%2,%3}, [%4];"
                    : "=r"(b[g * 2][0]), "=r"(b[g * 2][1]),
                      "=r"(b[g * 2 + 1][0]), "=r"(b[g * 2 + 1][1])
                    : "r"(addr));
            }
#pragma unroll
            for (int mi = 0; mi < 2; mi++)
#pragma unroll
                for (int ni = 0; ni < 8; ni++) {
                    asm volatile(
                        "mma.sync.aligned.m16n8k16.row.col.f32.bf16.bf16.f32 "
                        "{%0,%1,%2,%3}, {%4,%5,%6,%7}, {%8,%9}, {%0,%1,%2,%3};"
                        : "+f"(acc[mi][ni][0]), "+f"(acc[mi][ni][1]),
                          "+f"(acc[mi][ni][2]), "+f"(acc[mi][ni][3])
                        : "r"(a[mi][0]), "r"(a[mi][1]), "r"(a[mi][2]), "r"(a[mi][3]),
                          "r"(b[ni][0]), "r"(b[ni][1]));
                }
        }
    }

    // Epilogue: atomicAdd partials into out (zeroed by prep).
    // Bias added exactly once: by the (term 0, khalf 0) block.
    const bool addb = (term == 0) && (khalf == 0);
#pragma unroll
    for (int mi = 0; mi < 2; mi++) {
#pragma unroll
        for (int rp = 0; rp < 2; rp++) {
            int r = wm * 32 + mi * 16 + rp * 8 + (lane >> 2);
            int p = m_begin + r;
            if (p < m_end) {
                int bb = g_rows[p];
                float* op = out + (size_t)bb * OUT_DIM + n0 + wn * 64 + (lane & 3) * 2;
                const float* bp = bias + h * OUT_DIM + n0 + wn * 64 + (lane & 3) * 2;
#pragma unroll
                for (int ni = 0; ni < 8; ni++) {
                    float v0 = acc[mi][ni][rp * 2 + 0];
                    float v1 = acc[mi][ni][rp * 2 + 1];
                    if (addb) { v0 += bp[ni * 8 + 0]; v1 += bp[ni * 8 + 1]; }
                    atomicAdd(op + ni * 8 + 0, v0);
                    atomicAdd(op + ni * 8 + 1, v1);
                }
            }
        }
    }
}

extern "C" void kernel_launch(void* const* d_in, const int* in_sizes, int n_in,
                              void* d_out, int out_size) {
    const float* X     = (const float*)d_in[0];
    const int*   idx_w = (const int*)d_in[1];
    const float* W     = (const float*)d_in[2];
    const float* bias  = (const float*)d_in[3];
    float*       out   = (float*)d_out;

    const int Bn = in_sizes[1];

    const int XB = (Bn + 7) / 8;
    const int ZB = (int)(((long long)Bn * OUT_DIM / 4 + 1023) / 1024);
    prep<<<1 + XB + 512 + ZB, 256>>>(X, idx_w, W, out, Bn);

    long long extra = (long long)out_size - (long long)Bn * OUT_DIM;
    float* tail = nullptr;
    int mode = 0;
    if (extra >= Bn) {
        mode = (extra >= 2 * (long long)Bn) ? 2 : 1;
        tail = out + (size_t)Bn * OUT_DIM;
    }

    int m_slots = (Bn + 63) / 64;
    dim3 g(OUT_DIM / 128, m_slots, 6 * NHEADS + 1);
    gemm_mma<<<g, 128>>>(bias, out, Bn, idx_w, tail, mode);
}